// round 16
// baseline (speedup 1.0000x reference)
#include <cuda_runtime.h>

#define BB 512
#define SS 512
#define EE 64
#define BOSs 1
#define EOSs 2
#define NE 8     // normalize every 8 steps (deferred apply)
#define TPB 128  // 4 warps per sequence; lane-pair split of the i-range

// Scratch (device globals — allocation-free rule)
__device__ float g_val[BB];
__device__ unsigned int g_ctr = 0;

// ---------------------------------------------------------------------------
// Fused forward + score: 128 threads per sequence.
// Warp w owns states 16w..16w+15. Lanes (2k,2k+1) are halves 0/1 of state
// 16w+k over the i-range; half-combine is one __shfl_xor(1) — NO smem
// round-trip, ONE __syncthreads per step. 3.46 warps/SMSP chip-wide.
// ---------------------------------------------------------------------------
__global__ __launch_bounds__(TPB) void crf_fused(
    const float* __restrict__ em,     // [B,S,E]
    const float* __restrict__ T,      // [E,E]
    const int*   __restrict__ ent,    // [B,S]
    const int*   __restrict__ mask,   // [B,S] (bool as int32)
    float* __restrict__ out)
{
    __shared__ __align__(16) float abuf[2][EE];
    __shared__ float red[4];          // per-warp alpha-sum partials (2x dup)
    __shared__ float redz[4];         // final z partials
    __shared__ float reds[4];         // score partials
    __shared__ __align__(16) float Tsh[EE * EE];
    __shared__ __align__(16) int   esh[SS];
    __shared__ __align__(16) int   msh[SS];

    const int b    = blockIdx.x;
    const int tid  = threadIdx.x;
    const int lane = tid & 31;
    const int w    = tid >> 5;
    const int j    = 16 * w + (lane >> 1);   // state owned by this lane pair
    const int half = lane & 1;               // which half of the i-range
    const int ilo  = 32 * half;

    // Stage T, entities, mask into shared (coalesced vector loads).
    {
        const float4* Tg = reinterpret_cast<const float4*>(T);
        float4*       Ts = reinterpret_cast<float4*>(Tsh);
#pragma unroll
        for (int i = tid; i < EE * EE / 4; i += TPB) Ts[i] = Tg[i];
        const int4* eg = reinterpret_cast<const int4*>(ent + (size_t)b * SS);
        const int4* mg = reinterpret_cast<const int4*>(mask + (size_t)b * SS);
        int4* es = reinterpret_cast<int4*>(esh);
        int4* ms = reinterpret_cast<int4*>(msh);
#pragma unroll
        for (int i = tid; i < SS / 4; i += TPB) { es[i] = eg[i]; ms[i] = mg[i]; }
    }
    __syncthreads();

    // Half M-column for (half, j): 32 exp(T) values in registers.
    // exp(-10000) underflows to exactly 0 — matches logsumexp semantics.
    float Mc[32];
#pragma unroll
    for (int i = 0; i < 32; i++) Mc[i] = __expf(Tsh[(ilo + i) * EE + j]);

    const float* emb = em + (size_t)b * SS * EE;

    // t = 0: both lanes of a pair compute the same a (dup -> 0.5 factor on sums).
    float a    = __expf(Tsh[BOSs * EE + j] + emb[j]);
    float logC = 0.f;
    {
        float sw = a;
#pragma unroll
        for (int o = 16; o > 0; o >>= 1) sw += __shfl_xor_sync(0xffffffffu, sw, o);
        if (lane == 0) red[w] = sw;
        if (half == 0) abuf[0][j] = a;
    }
    __syncthreads();

    float accS  = 0.f;
    int   ep    = esh[0];
    int   lastE = ep;
    int   cur   = 0;
    float em_next = emb[EE + j];   // prefetch t=1 (consumed next iteration)

    for (int t = 1; t < SS; t++) {
        const float emv = em_next;
        if (t + 1 < SS) em_next = emb[(size_t)(t + 1) * EE + j];
        const float ex = __expf(emv);    // MUFU early, off the critical tail
        const int m = msh[t];
        const int e = esh[t];

        // Partial dot over this half's 32 i-values: 8 LDS.128, 4 FFMA chains.
        const float4* av = reinterpret_cast<const float4*>(abuf[cur] + ilo);
        float acc0 = 0.f, acc1 = 0.f, acc2 = 0.f, acc3 = 0.f;
#pragma unroll
        for (int i = 0; i < 8; i++) {
            const float4 v4 = av[i];
            acc0 = fmaf(v4.x, Mc[4 * i + 0], acc0);
            acc1 = fmaf(v4.y, Mc[4 * i + 1], acc1);
            acc2 = fmaf(v4.z, Mc[4 * i + 2], acc2);
            acc3 = fmaf(v4.w, Mc[4 * i + 3], acc3);
        }
        float part = (acc0 + acc1) + (acc2 + acc3);
        // Other half lives in the adjacent lane: one shuffle, no smem, no bar.
        part += __shfl_xor_sync(0xffffffffu, part, 1);
        float v = part * ex;

        // Deferred scale: first step after a norm step applies 1/S.
        if ((t & (NE - 1)) == 1) {
            const float s    = 0.5f * ((red[0] + red[1]) + (red[2] + red[3]));
            const float invS = 1.0f / s;
            logC += __logf(s);
            v *= invS;
            a = m ? v : a * invS;
        } else {
            a = m ? v : a;
        }

        // Fused path score: only the half-0 lane of the matching state adds.
        if (m) {
            if (half == 0 && j == e) accS += emv + Tsh[ep * EE + e];
            lastE = e;
        }
        ep = e;

        // Norm step: publish duplicated warp sums (consumed at t+1).
        if ((t & (NE - 1)) == 0) {
            float sw = a;
#pragma unroll
            for (int o = 16; o > 0; o >>= 1) sw += __shfl_xor_sync(0xffffffffu, sw, o);
            if (lane == 0) red[w] = sw;
        }

        if (half == 0) abuf[cur ^ 1][j] = a;
        __syncthreads();
        cur ^= 1;
    }

    // Finish: z = sum_j a_j * exp(T[j,EOS]) (dup pairs -> 0.5), plus score.
    {
        float z  = a * __expf(Tsh[j * EE + EOSs]);
        float sc = accS;
#pragma unroll
        for (int o = 16; o > 0; o >>= 1) {
            z  += __shfl_xor_sync(0xffffffffu, z, o);
            sc += __shfl_xor_sync(0xffffffffu, sc, o);
        }
        if (lane == 0) { redz[w] = z; reds[w] = sc; }
        __syncthreads();
        if (tid == 0) {
            const int e0 = esh[0];
            const float score = (reds[0] + reds[1]) + (reds[2] + reds[3])
                              + Tsh[BOSs * EE + e0] + emb[e0]
                              + Tsh[lastE * EE + EOSs];
            const float zz = 0.5f * ((redz[0] + redz[1]) + (redz[2] + redz[3]));
            g_val[b] = (logC + __logf(zz)) - score;
        }
    }

    // Last block to arrive does the mean-reduce (fixed order → deterministic).
    __threadfence();
    if (w == 0) {
        unsigned int tk = 0;
        if (lane == 0) tk = atomicAdd(&g_ctr, 1u);
        tk = __shfl_sync(0xffffffffu, tk, 0);
        if (tk == BB - 1) {
            __threadfence();
            float acc = 0.f;
#pragma unroll
            for (int i = 0; i < BB / 32; i++) acc += __ldcg(&g_val[i * 32 + lane]);
#pragma unroll
            for (int o = 16; o > 0; o >>= 1) acc += __shfl_xor_sync(0xffffffffu, acc, o);
            if (lane == 0) {
                out[0] = acc / (float)BB;
                g_ctr = 0;   // reset for next graph replay
            }
        }
    }
}

extern "C" void kernel_launch(void* const* d_in, const int* in_sizes, int n_in,
                              void* d_out, int out_size) {
    const float* emissions   = (const float*)d_in[0];
    const float* transitions = (const float*)d_in[1];
    const int*   entities    = (const int*)d_in[2];
    const int*   mask        = (const int*)d_in[3];
    float* out               = (float*)d_out;

    crf_fused<<<BB, TPB>>>(emissions, transitions, entities, mask, out);
}